// round 8
// baseline (speedup 1.0000x reference)
#include <cuda_runtime.h>
#include <math.h>

#define BATCH 8
#define REG   400
#define TLEN  1200
#define NB    5
#define NPSI  1024
#define LMAX  544

#define NOUT  TLEN
#define XOFF  288                  // left zero pad in shared X
#define SHX   1856
#define DMAX  576                  // padded taps per (b,k) in global
#define DSEG  150                  // staged tap-pairs per band (S6 <= 150)

static __device__ float d_D[BATCH * NB][DMAX];
static __device__ int   d_LD[BATCH * NB];   // kept tap count (<= 300)
static __device__ int   d_OFF[BATCH * NB];  // adjusted (off - 1)
static __device__ float d_SQS[BATCH * NB];  // sqrt(scale)

// ---------------------------------------------------------------------------
// packed fp32x2 helpers
// ---------------------------------------------------------------------------
__device__ __forceinline__ void fma2(unsigned long long &a,
                                     unsigned long long x,
                                     unsigned long long d) {
    asm("fma.rn.f32x2 %0, %1, %2, %0;" : "+l"(a) : "l"(x), "l"(d));
}
__device__ __forceinline__ unsigned long long lds64(unsigned sa) {
    unsigned long long v;
    asm("ld.shared.b64 %0, [%1];" : "=l"(v) : "r"(sa));
    return v;
}
__device__ __forceinline__ void lds128(unsigned sa, unsigned long long &a,
                                       unsigned long long &b) {
    asm("ld.shared.v2.u64 {%0,%1}, [%2];" : "=l"(a), "=l"(b) : "r"(sa));
}

// ---------------------------------------------------------------------------
// Kernel 1: INT_PSI (fp32 scan) + per-(b,k) taps + Gaussian-tail truncation
//           + freq bands.  576 threads per (b,k) block.
// ---------------------------------------------------------------------------
__global__ void k_prep(const float* __restrict__ tr,
                       const float* __restrict__ lsp,
                       const float* __restrict__ bwp,
                       float* __restrict__ out_bands) {
    __shared__ float sp[NPSI];
    __shared__ float shK[LMAX + 1];
    __shared__ float shDt[DMAX];
    __shared__ int   s_lo, s_hi;

    const int bk = blockIdx.x;
    const int b  = bk / NB;
    const int k  = bk % NB;
    const int i  = threadIdx.x;

    const float STEP_F = (float)(16.0 / 1023.0);

    // psi + inclusive scan (two values per thread since blockDim=576 < 1024)
    for (int idx = i; idx < NPSI; idx += DMAX) {
        float x = -8.0f + STEP_F * (float)idx;
        sp[idx] = expf(-0.5f * x * x) * cosf(5.0f * x);
    }
    __syncthreads();
    for (int o = 1; o < NPSI; o <<= 1) {
        float a0 = 0.0f, a1 = 0.0f;
        int i1 = i + DMAX;
        if (i >= o) a0 = sp[i - o];
        if (i1 < NPSI && i1 >= o) a1 = sp[i1 - o];
        __syncthreads();
        sp[i] += a0;
        if (i1 < NPSI) sp[i1] += a1;
        __syncthreads();
    }

    const float trf   = tr[b] / 2.0f;
    const float scale = expf(lsp[k]) / trf;
    const float sstep = scale * STEP_F;
    const int   L0    = (int)floorf(scale * 16.0f) + 2;

    bool m = false;
    if (i < LMAX) {
        int j = (int)floorf((float)i / sstep);
        m = (i < L0) && (j < NPSI);
        int jc = min(max(j, 0), NPSI - 1);
        shK[i] = m ? sp[jc] * STEP_F : 0.0f;
    } else if (i == LMAX) {
        shK[LMAX] = 0.0f;
    }
    if (i == 0) { s_lo = DMAX; s_hi = -1; }
    const int L = __syncthreads_count(m);   // mask is a prefix

    // full taps into shared
    float dv = 0.0f;
    if (i <= L) {
        float prev = (i == 0) ? 0.0f : shK[i - 1];
        dv = prev - shK[i];
    }
    shDt[i] = dv;
    __syncthreads();

    // significant range (exclude the boundary tap i == L; |D[L]| ~ 9.3e-6)
    const float thr = 1e-4f / scale;
    if (i < L && fabsf(shDt[i]) > thr) {
        atomicMin(&s_lo, i);
        atomicMax(&s_hi, i);
    }
    __syncthreads();

    int lo, hi;
    if (s_hi >= s_lo) { lo = s_lo & ~1; hi = s_hi; }
    else              { lo = 0;         hi = L;    }   // degenerate fallback
    hi = min(hi, lo + 2 * DSEG - 1);                   // capacity clamp
    const int newLD = hi - lo + 1;

    d_D[bk][i] = (i < newLD) ? shDt[i + lo] : 0.0f;    // i+lo <= hi < DMAX

    if (i == 0) {
        d_LD[bk]  = newLD;
        d_OFF[bk] = (L - 2) / 2 + 1 - L + lo;          // (off - 1) + lo
        d_SQS[bk] = sqrtf(scale);
        float center = 1.0f / (scale * tr[b]);
        float bw = bwp[k];
        out_bands[bk * 2 + 0] = fmaxf(0.008f, center * (1.0f - bw * 0.5f));
        out_bands[bk * 2 + 1] = fminf(0.12f,  center * (1.0f + bw * 0.5f));
    }
}

// ---------------------------------------------------------------------------
// Kernel 2: FIR, packed f32x2, polyphase-fused, software-pipelined D loads.
// All 5 bands' tap quads are pre-staged once; shV is double-buffered so each
// band costs exactly ONE __syncthreads.
// ---------------------------------------------------------------------------
__global__ void __launch_bounds__(128, 7)
k_cwt(const float* __restrict__ ts, float* __restrict__ out) {
    const int br  = blockIdx.x;
    const int b   = br / REG;
    const int tid = threadIdx.x;

    __shared__ __align__(16) float  shXA[SHX];
    __shared__ __align__(16) float  shXB[SHX + 2];
    __shared__ __align__(16) float4 shD5[NB * DSEG + 4]; // (De,De,Do,Do) quads
    __shared__ float shV[2][132];

    for (int idx = tid; idx < SHX; idx += 128) shXA[idx] = 0.0f;
    for (int idx = tid; idx < SHX + 2; idx += 128) shXB[idx] = 0.0f;
    __syncthreads();
    const float* __restrict__ xrow = ts + (size_t)br * TLEN;
    for (int idx = tid; idx < TLEN; idx += 128) {
        float v = xrow[idx];
        shXA[XOFF + idx]     = v;
        shXB[XOFF + idx + 1] = v;      // shXB[m] = Xext[m-1]
    }
    // stage ALL bands' tap quads once (+ zero the overrun pad)
    for (int idx = tid; idx < NB * DSEG + 4; idx += 128) {
        if (idx < NB * DSEG) {
            int band = idx / DSEG;
            int pr   = idx - band * DSEG;
            float2 p = ((const float2*)d_D[b * NB + band])[pr];
            shD5[idx] = make_float4(p.x, p.x, p.y, p.y);
        } else {
            shD5[idx] = make_float4(0.f, 0.f, 0.f, 0.f);
        }
    }
    __syncthreads();

    float* __restrict__ outbase = out + (size_t)br * NB * NOUT;

    const unsigned aXA = (unsigned)__cvta_generic_to_shared(shXA);
    const unsigned aXB = (unsigned)__cvta_generic_to_shared(shXB);
    const unsigned aD5 = (unsigned)__cvta_generic_to_shared(shD5);

    for (int k = 0; k < NB; k++) {
        const int   bk  = b * NB + k;
        const int   LD  = d_LD[bk];
        const int   off = d_OFF[bk];
        const float sq  = d_SQS[bk];

        const int  m0   = XOFF + off + 10 * tid;   // even-window base elem
        const bool even = ((m0 & 1) == 0);
        unsigned pX = even ? (aXA + 4u * (unsigned)m0)
                           : (aXB + 4u * (unsigned)(m0 + 1));
        unsigned pD = aD5 + (unsigned)k * (DSEG * 16);

        const int S  = (LD + 1) >> 1;              // tap pairs  (<= DSEG)
        const int S6 = ((S + 5) / 6) * 6;          // zero-tap padded

        unsigned long long E0 = 0, E1 = 0, E2 = 0, E3 = 0, E4 = 0;
        unsigned long long V0 = 0, V1 = 0, V2 = 0, V3 = 0, V4 = 0;

        unsigned long long W0 = lds64(pX + 0);
        unsigned long long W1 = lds64(pX + 8);
        unsigned long long W2 = lds64(pX + 16);
        unsigned long long W3 = lds64(pX + 24);
        unsigned long long W4 = lds64(pX + 32);
        unsigned long long W5 = lds64(pX + 40);

        unsigned long long dEa, dOa, dEb, dOb;
        lds128(pD, dEa, dOa);                      // step-0 quad preload

#define FMAS(Q0, Q1, Q2, Q3, Q4, DE, DO)                                 \
        fma2(E0, Q0, DE); fma2(V0, Q0, DO);                              \
        fma2(E1, Q1, DE); fma2(V1, Q1, DO);                              \
        fma2(E2, Q2, DE); fma2(V2, Q2, DO);                              \
        fma2(E3, Q3, DE); fma2(V3, Q3, DO);                              \
        fma2(E4, Q4, DE); fma2(V4, Q4, DO);

        for (int it = 0; it < S6; it += 6) {
            lds128(pD + 16, dEb, dOb);             // prefetch step 1
            FMAS(W0, W1, W2, W3, W4, dEa, dOa)     // step 0
            W0 = lds64(pX + 48);
            lds128(pD + 32, dEa, dOa);             // prefetch step 2
            FMAS(W1, W2, W3, W4, W5, dEb, dOb)     // step 1
            W1 = lds64(pX + 56);
            lds128(pD + 48, dEb, dOb);             // prefetch step 3
            FMAS(W2, W3, W4, W5, W0, dEa, dOa)     // step 2
            W2 = lds64(pX + 64);
            lds128(pD + 64, dEa, dOa);             // prefetch step 4
            FMAS(W3, W4, W5, W0, W1, dEb, dOb)     // step 3
            W3 = lds64(pX + 72);
            lds128(pD + 80, dEb, dOb);             // prefetch step 5
            FMAS(W4, W5, W0, W1, W2, dEa, dOa)     // step 4
            W4 = lds64(pX + 80);
            lds128(pD + 96, dEa, dOa);             // prefetch next group step 0
            FMAS(W5, W0, W1, W2, W3, dEb, dOb)     // step 5
            W5 = lds64(pX + 88);

            pX += 48;
            pD += 96;
        }
#undef FMAS

        // exchange V0.lo with neighbor thread (double-buffered -> 1 sync/band)
        float* shVk = shV[k & 1];
        shVk[tid] = ((float2*)&V0)->x;
        __syncthreads();

        if (tid < 120) {
            const float vlast = shVk[tid + 1];   // V[10t+10]
            float2* __restrict__ o2 =
                (float2*)(outbase + (size_t)k * NOUT + 10 * tid);
            float2 e, va, vb, r;
            e = *(float2*)&E0; va = *(float2*)&V0; vb = *(float2*)&V1;
            r.x = sq * fabsf(e.x + va.y); r.y = sq * fabsf(e.y + vb.x); o2[0] = r;
            e = *(float2*)&E1; va = vb; vb = *(float2*)&V2;
            r.x = sq * fabsf(e.x + va.y); r.y = sq * fabsf(e.y + vb.x); o2[1] = r;
            e = *(float2*)&E2; va = vb; vb = *(float2*)&V3;
            r.x = sq * fabsf(e.x + va.y); r.y = sq * fabsf(e.y + vb.x); o2[2] = r;
            e = *(float2*)&E3; va = vb; vb = *(float2*)&V4;
            r.x = sq * fabsf(e.x + va.y); r.y = sq * fabsf(e.y + vb.x); o2[3] = r;
            e = *(float2*)&E4; va = *(float2*)&V4;
            r.x = sq * fabsf(e.x + va.y); r.y = sq * fabsf(e.y + vlast); o2[4] = r;
        }
        // no second sync: next band writes the OTHER shV buffer; reuse of this
        // buffer at band k+2 is ordered by band k+1's barrier.
    }
}

// ---------------------------------------------------------------------------
extern "C" void kernel_launch(void* const* d_in, const int* in_sizes, int n_in,
                              void* d_out, int out_size) {
    (void)in_sizes; (void)n_in; (void)out_size;
    const float* ts  = (const float*)d_in[0];
    const float* tr  = (const float*)d_in[1];
    const float* lsp = (const float*)d_in[2];
    const float* bwp = (const float*)d_in[3];
    float* out = (float*)d_out;

    float* bands = out + (size_t)BATCH * REG * NB * NOUT;

    k_prep<<<BATCH * NB, DMAX>>>(tr, lsp, bwp, bands);
    k_cwt<<<BATCH * REG, 128>>>(ts, out);
}